// round 13
// baseline (speedup 1.0000x reference)
#include <cuda_runtime.h>
#include <cuda_bf16.h>

// S4 Vandermonde kernel: out[h,l] = 2*Re( sum_n Ceff[h,n] * w[h,n]^l )
//   w = exp(dtA), Ceff = Bc*Cc*(w-1)/A ;  H=512, NH=32, L=8192.
//
// R12 = R10 math and loop shape EXACTLY (order-2 Goertzel, static unroll-4
// main loop, direct exp/sincos seeding) with the geometry retuned for
// latency hiding: SPT 128 -> 64, grid 256 -> 512, __launch_bounds__(128,3).
// R10 ran 2 warps/SMSP and sat at issue=41% (latency-exposed, 41K cyc vs a
// 28K pipe floor). At occ 3 every SM runs 3 blocks concurrently (3 warps per
// SMSP fill the FFMA2 issue slots), then 68 SMs take one short 4th block.

#define HH 512
#define NHALF 32
#define LL 8192
#define SPT 64                       // recurrence steps per lane
#define WPB 4                        // warps per block
#define CHUNK (32 * SPT)             // 2048 l-values per warp
#define CHUNKS_PER_H (LL / CHUNK)    // 4

typedef unsigned long long u64;

__device__ __forceinline__ u64 pk2(float lo, float hi) {
    u64 r; asm("mov.b64 %0,{%1,%2};" : "=l"(r) : "f"(lo), "f"(hi)); return r;
}
__device__ __forceinline__ void upk2(u64 v, float& lo, float& hi) {
    asm("mov.b64 {%0,%1},%2;" : "=f"(lo), "=f"(hi) : "l"(v));
}
__device__ __forceinline__ u64 f2mul(u64 a, u64 b) {
    u64 r; asm("mul.rn.f32x2 %0,%1,%2;" : "=l"(r) : "l"(a), "l"(b)); return r;
}
__device__ __forceinline__ u64 f2fma(u64 a, u64 b, u64 c) {
    u64 r; asm("fma.rn.f32x2 %0,%1,%2,%3;" : "=l"(r) : "l"(a), "l"(b), "l"(c)); return r;
}
__device__ __forceinline__ u64 f2add(u64 a, u64 b) {
    u64 r; asm("add.rn.f32x2 %0,%1,%2;" : "=l"(r) : "l"(a), "l"(b)); return r;
}

__device__ __forceinline__ float2 cmulf(float2 a, float2 b) {
    return make_float2(fmaf(a.x, b.x, -a.y * b.y), fmaf(a.x, b.y, a.y * b.x));
}

// reduction tree over 16 packed pairs -> scalar (lo+hi)
__device__ __forceinline__ float sumtree16(const u64* R) {
    u64 s0 = f2add(R[0], R[8]);
    u64 s1 = f2add(R[1], R[9]);
    u64 s2 = f2add(R[2], R[10]);
    u64 s3 = f2add(R[3], R[11]);
    u64 s4 = f2add(R[4], R[12]);
    u64 s5 = f2add(R[5], R[13]);
    u64 s6 = f2add(R[6], R[14]);
    u64 s7 = f2add(R[7], R[15]);
    s0 = f2add(s0, s4); s1 = f2add(s1, s5);
    s2 = f2add(s2, s6); s3 = f2add(s3, s7);
    s0 = f2add(s0, s2); s1 = f2add(s1, s3);
    s0 = f2add(s0, s1);
    float lo, hi; upk2(s0, lo, hi);
    return lo + hi;
}

#define PI2_HI 6.2831854820251465f
#define PI2_LO (-1.7484561e-7f)
#define INV2PI 0.15915494309189535f

// accurate sin/cos with two-float 2*pi reduction
__device__ __forceinline__ void redsc(float th, float* s, float* c) {
    float kk = rintf(th * INV2PI);
    float r  = fmaf(-kk, PI2_HI, th);
    r        = fmaf(-kk, PI2_LO, r);
    __sincosf(r, s, c);
}

// per-mode start values from the smem param rows at offset l0f
__device__ __forceinline__ void start_mode(const float4* mpn, float l0f,
                                           float& r0, float& rm,
                                           float& p,  float& q) {
    float4 a = mpn[0];   // p, q, wm32r, wm32i
    float4 b = mpn[1];   // c2r, c2i, dre, dim
    p = a.x; q = a.y;
    float sn, cs;
    redsc(b.w * l0f, &sn, &cs);          // theta = dim*l0 (same rounding as ref)
    float mg  = __expf(b.z * l0f);       // dre*l0 <= 0 -> mg <= 1
    float zr  = mg * cs, zi = mg * sn;
    float z0r = fmaf(b.x, zr, -b.y * zi);
    float z0i = fmaf(b.x, zi,  b.y * zr);
    r0 = z0r;                            // r(l0)
    rm = fmaf(z0r, a.z, -z0i * a.w);     // Re(z0 * w^-32) = r(l0-32)
}

__global__ void __launch_bounds__(128, 3)
s4_vandermonde_kernel(const float* __restrict__ log_dt,
                      const float* __restrict__ log_A_real,
                      const float* __restrict__ A_imag,
                      const float* __restrict__ Bmat,
                      const float* __restrict__ Cmat,
                      float* __restrict__ out)
{
    // per warp, per mode: row0 = {p, q, wm32r, wm32i}, row1 = {c2r, c2i, dre, dim}
    __shared__ float4 mp[WPB][NHALF][2];

    const int w   = threadIdx.x >> 5;
    const int j   = threadIdx.x & 31;
    const int gw  = blockIdx.x * WPB + w;
    const int h   = gw >> 2;       // / CHUNKS_PER_H
    const int chk = gw & 3;

    // ---------- phase A: lane j computes mode j params (MUFU-heavy) ----------
    {
        const int n = j;
        const float dt  = __expf(log_dt[h]);
        const float ar  = -__expf(log_A_real[h * NHALF + n]);
        const float aiv = -A_imag[h * NHALF + n];
        const float dre = dt * ar;
        const float dim = dt * aiv;

        // w^32 -> p, q; w^-32 (magnitude clamped; when clamped q underflowed to 0)
        float s32, c32; redsc(32.f * dim, &s32, &c32);
        float mg32 = __expf(32.f * dre);
        float w32r = mg32 * c32, w32i = mg32 * s32;
        float p = w32r + w32r;
        float q = -fmaf(w32r, w32r, w32i * w32i);
        float mgm = __expf(fminf(-32.f * dre, 60.f));
        float wmr = mgm * c32, wmi = -mgm * s32;
        // 2*Ceff = 2*Bc*Cc*(w^1 - 1)/A
        float s1v, c1v; redsc(dim, &s1v, &c1v);
        float mg1 = __expf(dre);
        float2 w1  = make_float2(mg1 * c1v, mg1 * s1v);
        float2 num = make_float2(w1.x - 1.0f, w1.y);
        float  inv = 2.0f / fmaf(ar, ar, aiv * aiv);
        float2 ia  = make_float2(ar * inv, -aiv * inv);
        const float2* Bv = (const float2*)Bmat;
        const float2* Cv = (const float2*)Cmat;
        float2 bc  = cmulf(Bv[h * NHALF + n], Cv[h * NHALF + n]);
        float2 c2  = cmulf(cmulf(bc, num), ia);

        mp[w][n][0] = make_float4(p, q, wmr, wmi);
        mp[w][n][1] = make_float4(c2.x, c2.y, dre, dim);
    }
    __syncwarp();

    // ---------- phase B: direct seed at l0 = chk*2048 + j ----------
    const float l0f = (float)(chk * CHUNK + j);
    u64 RB[NHALF / 2], RA[NHALF / 2], P[NHALF / 2], Q[NHALF / 2];
    #pragma unroll
    for (int m = 0; m < NHALF / 2; m++) {
        float r0a, rma, pa, qa, r0b, rmb, pb, qb;
        start_mode(&mp[w][2 * m][0],     l0f, r0a, rma, pa, qa);
        start_mode(&mp[w][2 * m + 1][0], l0f, r0b, rmb, pb, qb);
        RB[m] = pk2(r0a, r0b);        // r_0
        RA[m] = pk2(rma, rmb);        // r_-1
        P[m]  = pk2(pa, pb);
        Q[m]  = pk2(qa, qb);
    }

    // ---------- main recurrence, unrolled by 2 with role swap (R6/R10 body) ----------
    float* op = out + h * LL + chk * CHUNK + j;
    #pragma unroll 4
    for (int i = 0; i < SPT; i += 2) {
        op[i * 32] = sumtree16(RB);                   // r_i
        #pragma unroll
        for (int m = 0; m < NHALF / 2; m++)           // RA <- r_{i+1}
            RA[m] = f2fma(P[m], RB[m], f2mul(Q[m], RA[m]));
        op[(i + 1) * 32] = sumtree16(RA);             // r_{i+1}
        #pragma unroll
        for (int m = 0; m < NHALF / 2; m++)           // RB <- r_{i+2}
            RB[m] = f2fma(P[m], RA[m], f2mul(Q[m], RB[m]));
    }
}

extern "C" void kernel_launch(void* const* d_in, const int* in_sizes, int n_in,
                              void* d_out, int out_size)
{
    const float* log_dt     = (const float*)d_in[0];
    const float* log_A_real = (const float*)d_in[1];
    const float* A_imag     = (const float*)d_in[2];
    const float* Bmat       = (const float*)d_in[3];
    const float* Cmat       = (const float*)d_in[4];
    float* out = (float*)d_out;

    dim3 grid(HH * CHUNKS_PER_H / WPB);   // 512 blocks
    dim3 block(32 * WPB);                 // 128 threads
    s4_vandermonde_kernel<<<grid, block>>>(log_dt, log_A_real, A_imag,
                                           Bmat, Cmat, out);
}